// round 16
// baseline (speedup 1.0000x reference)
#include <cuda_runtime.h>
#include <math_constants.h>

// Problem constants (from reference setup_inputs)
#define N_IMG 2
#define C_CH  256
#define H_F   64
#define W_F   64
#define HW    (H_F * W_F)
#define R_ROI 128
#define PH    7
#define PW    7
#define NBINS (PH * PW)   // 49
#define SCALE 0.0625f
#define C4    (C_CH / 4)       // 64 float4 per pixel
#define ROWSTRIDE4 (W_F * C4)  // 4096 float4 per feature row
#define FULLMASK 0xffffffffu

// NHWC scratch: [b][h][w][c], 8 MB
__device__ float TFEAT[N_IMG * HW * C_CH];
// packed bounds per (r, bin): b<<28 | hs<<21 | he<<14 | ws<<7 | we
__device__ unsigned int BNDS[R_ROI * NBINS];

// ---------------------------------------------------------------------------
// Kernel 1: NCHW -> NHWC transpose (float4 both sides) + bounds precompute
// folded into the first 25 blocks. Bounds arithmetic VERBATIM bit-exact.
// ---------------------------------------------------------------------------
__global__ __launch_bounds__(256) void transpose_kernel(const float* __restrict__ feat,
                                                        const float* __restrict__ rois)
{
    __shared__ float tile[32][33];
    int b   = blockIdx.z;
    int hw0 = blockIdx.x * 32;
    int c0  = blockIdx.y * 32;
    int tx  = threadIdx.x;   // 0..7
    int ty  = threadIdx.y;   // 0..31
    int tid = ty * 8 + tx;

    if (blockIdx.y == 0 && blockIdx.z == 0 && blockIdx.x < 25) {
        int idx = blockIdx.x * 256 + tid;
        if (idx < R_ROI * NBINS) {
            int r   = idx / NBINS;
            int bin = idx - r * NBINS;
            int ph  = bin / PW;
            int pw  = bin - ph * PW;

            const float* roi = rois + r * 5;
            int bb = (int)roi[0];
            int sw = (int)rintf(roi[1] * SCALE);
            int sh_ = (int)rintf(roi[2] * SCALE);
            int ew = (int)rintf(roi[3] * SCALE);
            int eh = (int)rintf(roi[4] * SCALE);

            float roi_w = (float)max(ew - sw + 1, 1);
            float roi_h = (float)max(eh - sh_ + 1, 1);
            float bin_h = roi_h * (1.0f / PH);   // bit-exact vs reference
            float bin_w = roi_w * (1.0f / PW);

            int hs = min(max((int)floorf((float)ph * bin_h) + sh_, 0), H_F);
            int he = min(max((int)ceilf(((float)ph + 1.0f) * bin_h) + sh_, 0), H_F);
            int ws = min(max((int)floorf((float)pw * bin_w) + sw, 0), W_F);
            int we = min(max((int)ceilf(((float)pw + 1.0f) * bin_w) + sw, 0), W_F);

            BNDS[idx] = ((unsigned)bb << 28) | ((unsigned)hs << 21) |
                        ((unsigned)he << 14) | ((unsigned)ws << 7) | (unsigned)we;
        }
    }

    const float4* src4 = (const float4*)(feat + (size_t)b * C_CH * HW);
    float4*       dst4 = (float4*)(TFEAT + (size_t)b * HW * C_CH);

    float4 v = src4[(size_t)(c0 + ty) * (HW / 4) + (hw0 / 4) + tx];
    tile[ty][4 * tx + 0] = v.x;
    tile[ty][4 * tx + 1] = v.y;
    tile[ty][4 * tx + 2] = v.z;
    tile[ty][4 * tx + 3] = v.w;
    __syncthreads();

    float4 o;
    o.x = tile[4 * tx + 0][ty];
    o.y = tile[4 * tx + 1][ty];
    o.z = tile[4 * tx + 2][ty];
    o.w = tile[4 * tx + 3][ty];
    dst4[(size_t)(hw0 + ty) * C4 + (c0 / 4) + tx] = o;
}

// ---------------------------------------------------------------------------
// Kernel 2: pool, flattened-pixel decomposition.
// Warp = (r, bin, 32-ch slice). Lane octets cover 4 DIFFERENT pixels per
// LDG.128 (lane>>3 = pixel-in-group, lane&7 = float4 within 32 channels).
// The bin's bh*bw pixels flatten to ceil(n/4) loads whose addresses depend
// only on the loop index -> all loads independent; depth-2 rotation keeps
// them streaming (one latency exposure for the avg 3-load bin).
// p -> (h,w) via (p+0.5)*rcp(bw) floor (exact for p<2^12, bw<=64).
// Tail pixels clamp to p=n-1 (max idempotent). shfl_xor(8,16) folds the
// 4 pixel groups; empty bins -> 0.
// Block = (r, eighth, g): 7 warps = the 7 bins of ph row g. Grid 7168.
// ---------------------------------------------------------------------------
__global__ __launch_bounds__(224) void pool_kernel(float* __restrict__ out)
{
    __shared__ float sh[PH][36];     // [bin_local][32ch + pad] (rows 144B)

    int blk  = blockIdx.x;           // r*56 + e*7 + g
    int g    = blk % 7;
    int e    = (blk / 7) & 7;        // channel-eighth (32 ch)
    int r    = blk / 56;
    int tid  = threadIdx.x;
    int warp = tid >> 5;             // 0..6 = pw (ph = g)
    int lane = tid & 31;
    int pix0 = lane >> 3;            // 0..3: pixel within load-group
    int cidx = lane & 7;             // float4 within the 32-ch slice

    unsigned bnd = __ldg(&BNDS[r * NBINS + g * 7 + warp]);
    int we = bnd & 0x7f;
    int ws = (bnd >> 7) & 0x7f;
    int he = (bnd >> 14) & 0x7f;
    int hs = (bnd >> 21) & 0x7f;
    int b  = bnd >> 28;

    float4 ma;
    if ((he <= hs) || (we <= ws)) {
        ma = make_float4(0.f, 0.f, 0.f, 0.f);
    } else {
        int bw = we - ws;
        int n  = (he - hs) * bw;             // exact pixel count
        float invbw = 1.0f / (float)bw;
        int nloads = (n + 3) >> 2;
        const float4* base = (const float4*)TFEAT
                           + (b * HW * C4 + e * 8 + cidx)
                           + hs * ROWSTRIDE4 + ws * C4;

        ma = make_float4(-CUDART_INF_F, -CUDART_INF_F, -CUDART_INF_F, -CUDART_INF_F);

        // depth-2 rotation: next load issues before current is consumed
        int p = min(pix0, n - 1);
        int hh = (int)(((float)p + 0.5f) * invbw);
        int wp = p - hh * bw;
        float4 A = __ldg(base + hh * ROWSTRIDE4 + wp * C4);

        for (int i = 1; i < nloads; ++i) {
            int p2 = min(4 * i + pix0, n - 1);
            int h2 = (int)(((float)p2 + 0.5f) * invbw);
            int w2 = p2 - h2 * bw;
            float4 B = __ldg(base + h2 * ROWSTRIDE4 + w2 * C4);
            ma.x = fmaxf(ma.x, A.x);
            ma.y = fmaxf(ma.y, A.y);
            ma.z = fmaxf(ma.z, A.z);
            ma.w = fmaxf(ma.w, A.w);
            A = B;
        }
        ma.x = fmaxf(ma.x, A.x);
        ma.y = fmaxf(ma.y, A.y);
        ma.z = fmaxf(ma.z, A.z);
        ma.w = fmaxf(ma.w, A.w);

        // fold the 4 pixel groups (lanes differing in bits 3,4)
        ma.x = fmaxf(ma.x, __shfl_xor_sync(FULLMASK, ma.x, 8));
        ma.y = fmaxf(ma.y, __shfl_xor_sync(FULLMASK, ma.y, 8));
        ma.z = fmaxf(ma.z, __shfl_xor_sync(FULLMASK, ma.z, 8));
        ma.w = fmaxf(ma.w, __shfl_xor_sync(FULLMASK, ma.w, 8));
        ma.x = fmaxf(ma.x, __shfl_xor_sync(FULLMASK, ma.x, 16));
        ma.y = fmaxf(ma.y, __shfl_xor_sync(FULLMASK, ma.y, 16));
        ma.z = fmaxf(ma.z, __shfl_xor_sync(FULLMASK, ma.z, 16));
        ma.w = fmaxf(ma.w, __shfl_xor_sync(FULLMASK, ma.w, 16));
    }

    if (pix0 == 0)
        *(float4*)&sh[warp][cidx * 4] = ma;
    __syncthreads();

    // writeback: out[r][e*32 + c][g*7 + binl]; 32 runs of 7 floats,
    // 224 elems = 1 per thread. c = tid/7, binl = tid%7.
    int c    = tid / 7;
    int binl = tid - c * 7;
    out[((size_t)r * C_CH + e * 32 + c) * NBINS + g * 7 + binl] = sh[binl][c];
}

extern "C" void kernel_launch(void* const* d_in, const int* in_sizes, int n_in,
                              void* d_out, int out_size)
{
    const float* feat = (const float*)d_in[0];
    const float* rois = (const float*)d_in[1];
    float* out = (float*)d_out;

    dim3 tgrid(HW / 32, C_CH / 32, N_IMG);
    dim3 tblock(8, 32);
    transpose_kernel<<<tgrid, tblock>>>(feat, rois);

    pool_kernel<<<R_ROI * 8 * 7, 224>>>(out);
}

// round 17
// speedup vs baseline: 1.2369x; 1.2369x over previous
#include <cuda_runtime.h>
#include <math_constants.h>

// Problem constants (from reference setup_inputs)
#define N_IMG 2
#define C_CH  256
#define H_F   64
#define W_F   64
#define HW    (H_F * W_F)
#define R_ROI 128
#define PH    7
#define PW    7
#define NBINS (PH * PW)   // 49
#define SCALE 0.0625f
#define C4    (C_CH / 4)       // 64 float4 per pixel
#define ROWSTRIDE4 (W_F * C4)  // 4096 float4 per feature row
#define FULLMASK 0xffffffffu

// NHWC scratch: [b][h][w][c], 8 MB
__device__ float TFEAT[N_IMG * HW * C_CH];
// packed bounds per (r, bin): b<<28 | hs<<21 | he<<14 | ws<<7 | we
__device__ unsigned int BNDS[R_ROI * NBINS];

// ---------------------------------------------------------------------------
// Kernel 1: NCHW -> NHWC transpose (float4 both sides) + bounds precompute
// folded into the first 25 blocks. Bounds arithmetic VERBATIM bit-exact.
// ---------------------------------------------------------------------------
__global__ __launch_bounds__(256) void transpose_kernel(const float* __restrict__ feat,
                                                        const float* __restrict__ rois)
{
    __shared__ float tile[32][33];
    int b   = blockIdx.z;
    int hw0 = blockIdx.x * 32;
    int c0  = blockIdx.y * 32;
    int tx  = threadIdx.x;   // 0..7
    int ty  = threadIdx.y;   // 0..31
    int tid = ty * 8 + tx;

    if (blockIdx.y == 0 && blockIdx.z == 0 && blockIdx.x < 25) {
        int idx = blockIdx.x * 256 + tid;
        if (idx < R_ROI * NBINS) {
            int r   = idx / NBINS;
            int bin = idx - r * NBINS;
            int ph  = bin / PW;
            int pw  = bin - ph * PW;

            const float* roi = rois + r * 5;
            int bb = (int)roi[0];
            int sw = (int)rintf(roi[1] * SCALE);
            int sh_ = (int)rintf(roi[2] * SCALE);
            int ew = (int)rintf(roi[3] * SCALE);
            int eh = (int)rintf(roi[4] * SCALE);

            float roi_w = (float)max(ew - sw + 1, 1);
            float roi_h = (float)max(eh - sh_ + 1, 1);
            float bin_h = roi_h * (1.0f / PH);   // bit-exact vs reference
            float bin_w = roi_w * (1.0f / PW);

            int hs = min(max((int)floorf((float)ph * bin_h) + sh_, 0), H_F);
            int he = min(max((int)ceilf(((float)ph + 1.0f) * bin_h) + sh_, 0), H_F);
            int ws = min(max((int)floorf((float)pw * bin_w) + sw, 0), W_F);
            int we = min(max((int)ceilf(((float)pw + 1.0f) * bin_w) + sw, 0), W_F);

            BNDS[idx] = ((unsigned)bb << 28) | ((unsigned)hs << 21) |
                        ((unsigned)he << 14) | ((unsigned)ws << 7) | (unsigned)we;
        }
    }

    const float4* src4 = (const float4*)(feat + (size_t)b * C_CH * HW);
    float4*       dst4 = (float4*)(TFEAT + (size_t)b * HW * C_CH);

    float4 v = src4[(size_t)(c0 + ty) * (HW / 4) + (hw0 / 4) + tx];
    tile[ty][4 * tx + 0] = v.x;
    tile[ty][4 * tx + 1] = v.y;
    tile[ty][4 * tx + 2] = v.z;
    tile[ty][4 * tx + 3] = v.w;
    __syncthreads();

    float4 o;
    o.x = tile[4 * tx + 0][ty];
    o.y = tile[4 * tx + 1][ty];
    o.z = tile[4 * tx + 2][ty];
    o.w = tile[4 * tx + 3][ty];
    dst4[(size_t)(hw0 + ty) * C4 + (c0 / 4) + tx] = o;
}

// ---------------------------------------------------------------------------
// Kernel 2: pool, flattened-pixel stream at (r, bin, 128ch-half) granularity.
// Block = (r, half, g): 7 warps = the 7 bins of ph row g. 12544 warp-tasks.
// Iteration i covers pixels 2i (lanes 0-15) and 2i+1 (lanes 16-31); each
// iteration issues 2 INDEPENDENT LDG.128 (ch-lo quads q, ch-hi quads q+16
// of this 128-ch half), depth-2 rotated -> continuous load stream, one
// latency exposure for the avg 5-iteration bin. Exact-area reads (tail
// pixel clamped; max idempotent). p -> (h,w) via (p+0.5)*invbw floor
// (validated bit-exact in round 16). xor(16) folds the two pixel streams.
// ---------------------------------------------------------------------------
__global__ __launch_bounds__(224) void pool_kernel(float* __restrict__ out)
{
    __shared__ float sh[PH][132];    // [bin_local][128ch + pad]

    int blk  = blockIdx.x;           // r*14 + half*7 + g
    int g    = blk % 7;
    int half = (blk / 7) & 1;
    int r    = blk / 14;
    int tid  = threadIdx.x;
    int warp = tid >> 5;             // 0..6 = pw (ph = g)
    int lane = tid & 31;
    int q16  = lane & 15;            // float4 within the 64-ch group
    int pxs  = lane >> 4;            // 0/1: pixel stream select

    unsigned bnd = __ldg(&BNDS[r * NBINS + g * 7 + warp]);
    int we = bnd & 0x7f;
    int ws = (bnd >> 7) & 0x7f;
    int he = (bnd >> 14) & 0x7f;
    int hs = (bnd >> 21) & 0x7f;
    int b  = bnd >> 28;

    float4 aLo, aHi;
    if ((he <= hs) || (we <= ws)) {
        aLo = make_float4(0.f, 0.f, 0.f, 0.f);
        aHi = aLo;
    } else {
        int bw     = we - ws;
        int n      = (he - hs) * bw;         // exact pixel count
        float invbw = 1.0f / (float)bw;
        int rowadj = W_F - bw;               // pixel-index row correction
        // base at (hs, ws), this half's ch-lo group, lane's quad
        const float4* base = (const float4*)TFEAT
                           + (b * HW * C4 + half * 32 + q16)
                           + hs * ROWSTRIDE4 + ws * C4;

        aLo = make_float4(-CUDART_INF_F, -CUDART_INF_F, -CUDART_INF_F, -CUDART_INF_F);
        aHi = aLo;

        int nit = (n + 1) >> 1;

        // peeled first iteration (depth-2 rotation)
        int p  = min(pxs, n - 1);
        int h  = (int)(((float)p + 0.5f) * invbw);
        int off = (p + h * rowadj) * C4;
        float4 A0 = __ldg(base + off);
        float4 A1 = __ldg(base + off + 16);

        for (int i = 1; i < nit; ++i) {
            int p2 = min(2 * i + pxs, n - 1);
            int h2 = (int)(((float)p2 + 0.5f) * invbw);
            int off2 = (p2 + h2 * rowadj) * C4;
            float4 B0 = __ldg(base + off2);
            float4 B1 = __ldg(base + off2 + 16);

            aLo.x = fmaxf(aLo.x, A0.x); aLo.y = fmaxf(aLo.y, A0.y);
            aLo.z = fmaxf(aLo.z, A0.z); aLo.w = fmaxf(aLo.w, A0.w);
            aHi.x = fmaxf(aHi.x, A1.x); aHi.y = fmaxf(aHi.y, A1.y);
            aHi.z = fmaxf(aHi.z, A1.z); aHi.w = fmaxf(aHi.w, A1.w);

            A0 = B0; A1 = B1;
        }
        aLo.x = fmaxf(aLo.x, A0.x); aLo.y = fmaxf(aLo.y, A0.y);
        aLo.z = fmaxf(aLo.z, A0.z); aLo.w = fmaxf(aLo.w, A0.w);
        aHi.x = fmaxf(aHi.x, A1.x); aHi.y = fmaxf(aHi.y, A1.y);
        aHi.z = fmaxf(aHi.z, A1.z); aHi.w = fmaxf(aHi.w, A1.w);

        // fold the two pixel streams (lane i <-> i+16, same channels)
        aLo.x = fmaxf(aLo.x, __shfl_xor_sync(FULLMASK, aLo.x, 16));
        aLo.y = fmaxf(aLo.y, __shfl_xor_sync(FULLMASK, aLo.y, 16));
        aLo.z = fmaxf(aLo.z, __shfl_xor_sync(FULLMASK, aLo.z, 16));
        aLo.w = fmaxf(aLo.w, __shfl_xor_sync(FULLMASK, aLo.w, 16));
        aHi.x = fmaxf(aHi.x, __shfl_xor_sync(FULLMASK, aHi.x, 16));
        aHi.y = fmaxf(aHi.y, __shfl_xor_sync(FULLMASK, aHi.y, 16));
        aHi.z = fmaxf(aHi.z, __shfl_xor_sync(FULLMASK, aHi.z, 16));
        aHi.w = fmaxf(aHi.w, __shfl_xor_sync(FULLMASK, aHi.w, 16));
    }

    if (pxs == 0) {
        *(float4*)&sh[warp][q16 * 4]      = aLo;   // ch quads 0..15 of half
        *(float4*)&sh[warp][64 + q16 * 4] = aHi;   // ch quads 16..31
    }
    __syncthreads();

    // writeback: out[r][half*128 + c][g*7 + binl], 128 runs of 7 floats.
    // stride 224 = 32*7 -> binl invariant, c += 32 per iteration.
    float* dst = out + (size_t)r * C_CH * NBINS + (size_t)half * 128 * NBINS + g * 7;
    int c0   = tid / 7;          // 0..31
    int binl = tid - c0 * 7;     // 0..6
    #pragma unroll
    for (int it = 0; it < 4; ++it) {
        int c = c0 + it * 32;
        dst[c * NBINS + binl] = sh[binl][c];
    }
}

extern "C" void kernel_launch(void* const* d_in, const int* in_sizes, int n_in,
                              void* d_out, int out_size)
{
    const float* feat = (const float*)d_in[0];
    const float* rois = (const float*)d_in[1];
    float* out = (float*)d_out;

    dim3 tgrid(HW / 32, C_CH / 32, N_IMG);
    dim3 tblock(8, 32);
    transpose_kernel<<<tgrid, tblock>>>(feat, rois);

    pool_kernel<<<R_ROI * 2 * 7, 224>>>(out);
}